// round 1
// baseline (speedup 1.0000x reference)
#include <cuda_runtime.h>

#define BB 64
#define PP 24564
#define MM 50
#define CC 21
#define GX ((PP + 255) / 256)

// ---- scratch (static __device__; no allocation anywhere) ----
__device__ unsigned long long g_bp[BB * MM];     // packed (iou_bits<<32)|(~p) best prior per GT
__device__ int    g_bt_idx[BB * PP];             // best GT per prior (pre force-match)
__device__ float  g_bt_iou[BB * PP];             // best IoU per prior (pre force-match)
__device__ double g_loc_sum;
__device__ double g_conf_sum;
__device__ int    g_npos;

// ---------------------------------------------------------------------------
__global__ void k_init() {
    int i = blockIdx.x * blockDim.x + threadIdx.x;
    if (i < BB * MM) g_bp[i] = 0ull;
    if (i == 0) { g_loc_sum = 0.0; g_conf_sum = 0.0; g_npos = 0; }
}

// ---------------------------------------------------------------------------
// Matching: per (batch, prior) compute best GT (argmax over M, first-max) and
// contribute to per-GT best prior (argmax over P, lowest-p tiebreak).
__global__ void __launch_bounds__(256) k_match(const float4* __restrict__ dbox,
                                               const float4* __restrict__ gt)
{
    __shared__ float4 s_g[MM];
    __shared__ float  s_a[MM];
    __shared__ unsigned long long s_best[MM];

    int tid = threadIdx.x;
    int b = blockIdx.y;
    if (tid < MM) {
        float4 g = gt[b * MM + tid];
        s_g[tid] = g;
        s_a[tid] = (g.z - g.x) * (g.w - g.y);
        s_best[tid] = 0ull;
    }
    __syncthreads();

    int p = blockIdx.x * 256 + tid;
    if (p < PP) {
        float4 d = dbox[p];
        float a1 = (d.z - d.x) * (d.w - d.y);
        float best = -1.0f;
        int bm = 0;
        unsigned inv_p = 0xFFFFFFFFu - (unsigned)p;
        #pragma unroll 10
        for (int m = 0; m < MM; m++) {
            float4 g = s_g[m];
            float ix0 = fmaxf(d.x, g.x);
            float iy0 = fmaxf(d.y, g.y);
            float ix1 = fminf(d.z, g.z);
            float iy1 = fminf(d.w, g.w);
            float iw = fmaxf(ix1 - ix0, 0.0f);
            float ih = fmaxf(iy1 - iy0, 0.0f);
            float inter = iw * ih;
            float uni = a1 + s_a[m] - inter;
            float iou = __fdividef(inter, uni);     // uni > 0 always (valid boxes)
            if (iou > best) { best = iou; bm = m; } // strict > == first-max (jnp.argmax)
            // per-GT best: cheap guard on high word (monotone non-neg float bits),
            // stale reads only under-admit the guard, never skip a needed update
            float cur = __uint_as_float(((const unsigned*)&s_best[m])[1]);
            if (iou > cur) {
                unsigned long long pk =
                    ((unsigned long long)__float_as_uint(iou) << 32) | inv_p;
                atomicMax(&s_best[m], pk);
            }
        }
        g_bt_idx[b * PP + p] = bm;
        g_bt_iou[b * PP + p] = best;
    }
    __syncthreads();
    if (tid < MM) atomicMax(&g_bp[b * MM + tid], s_best[tid]);
}

// ---------------------------------------------------------------------------
// Fused: force-match fixups + labels + focal loss + GIoU loc loss + reductions.
__global__ void __launch_bounds__(256) k_loss(const float4* __restrict__ loc,
                                              const float*  __restrict__ conf,
                                              const float4* __restrict__ dbox,
                                              const float4* __restrict__ gt,
                                              const int*    __restrict__ glab)
{
    __shared__ float4 s_g[MM];
    __shared__ int    s_lab[MM];
    __shared__ int    s_bp[MM];
    __shared__ float  s_conf[256 * CC];   // 21 KB staging
    __shared__ float  s_red[16];
    __shared__ int    s_redi[8];

    int tid = threadIdx.x;
    int b = blockIdx.y;
    int p0 = blockIdx.x * 256;
    int rows = min(256, PP - p0);

    if (tid < MM) {
        s_g[tid]   = gt[b * MM + tid];
        s_lab[tid] = glab[b * MM + tid];
        unsigned long long pk = g_bp[b * MM + tid];
        s_bp[tid]  = (int)(0xFFFFFFFFu - (unsigned)(pk & 0xFFFFFFFFull));
    }
    // stage conf rows (fully coalesced)
    {
        size_t base = ((size_t)b * PP + (size_t)p0) * CC;
        int n = rows * CC;
        for (int i = tid; i < n; i += 256) s_conf[i] = conf[base + i];
    }
    __syncthreads();

    float fl = 0.0f, ll = 0.0f;
    int pos = 0;
    int p = p0 + tid;
    if (tid < rows) {
        int   idx = g_bt_idx[b * PP + p];
        float iou = g_bt_iou[b * PP + p];
        // force-match: last m wins (scatter duplicate-index semantics)
        #pragma unroll
        for (int m = 0; m < MM; m++)
            if (s_bp[m] == p) { idx = m; iou = 2.0f; }
        int lab = (iou < 0.5f) ? 0 : s_lab[idx];
        pos = (lab > 0) ? 1 : 0;

        // focal loss (logsumexp over 21 classes), stride-21 LDS is conflict-free
        const float* row = &s_conf[tid * CC];
        float mx = row[0];
        #pragma unroll
        for (int c = 1; c < CC; c++) mx = fmaxf(mx, row[c]);
        float sum = 0.0f;
        #pragma unroll
        for (int c = 0; c < CC; c++) sum += __expf(row[c] - mx);
        float ce = mx + __logf(sum) - row[lab];
        float pt = __expf(-ce);
        float om = fmaxf(1.0f - pt, 0.0f);       // clamp: fast-exp can give pt>1 by ~1e-6
        fl = 0.5f * om * sqrtf(om) * ce;         // ALPHA*(1-pt)^GAMMA*ce, GAMMA=1.5

        if (pos) {
            float4 d = dbox[p];
            float4 g = s_g[idx];
            float dw = d.z - d.x, dh = d.w - d.y;
            float dcx = d.x + 0.5f * dw, dcy = d.y + 0.5f * dh;
            float gw = g.z - g.x, gh = g.w - g.y;
            float gcx = g.x + 0.5f * gw, gcy = g.y + 0.5f * gh;
            // encode (EPS8 = 1e-8)
            float ex = __fdividef(gcx - dcx, dw + 1e-8f);
            float ey = __fdividef(gcy - dcy, dh + 1e-8f);
            float ew = __logf(__fdividef(gw, dw + 1e-8f) + 1e-8f);
            float eh = __logf(__fdividef(gh, dh + 1e-8f) + 1e-8f);
            // decode target against anchor
            float tcx = ex * dw + dcx, tcy = ey * dh + dcy;
            float tw = __expf(ew) * dw, th = __expf(eh) * dh;
            float tx0 = tcx - 0.5f * tw, ty0 = tcy - 0.5f * th;
            float tx1 = tcx + 0.5f * tw, ty1 = tcy + 0.5f * th;
            // decode prediction
            float4 l = loc[(size_t)b * PP + p];
            float pcx = l.x * dw + dcx, pcy = l.y * dh + dcy;
            float pw = __expf(l.z) * dw, ph = __expf(l.w) * dh;
            float px0 = pcx - 0.5f * pw, py0 = pcy - 0.5f * ph;
            float px1 = pcx + 0.5f * pw, py1 = pcy + 0.5f * ph;
            // GIoU (EPS7 = 1e-7)
            float ix0 = fmaxf(px0, tx0), iy0 = fmaxf(py0, ty0);
            float ix1 = fminf(px1, tx1), iy1 = fminf(py1, ty1);
            float iw = fmaxf(ix1 - ix0, 0.0f), ih = fmaxf(iy1 - iy0, 0.0f);
            float inter = iw * ih;
            float pa = (px1 - px0) * (py1 - py0);
            float ta = (tx1 - tx0) * (ty1 - ty0);
            float uni = pa + ta - inter;
            float i2 = __fdividef(inter, uni + 1e-7f);
            float e0x = fminf(px0, tx0), e0y = fminf(py0, ty0);
            float e1x = fmaxf(px1, tx1), e1y = fmaxf(py1, ty1);
            float ewd = fmaxf(e1x - e0x, 0.0f), ehd = fmaxf(e1y - e0y, 0.0f);
            float encl = ewd * ehd;
            float giou = i2 - __fdividef(encl - uni, encl + 1e-7f);
            ll = 1.0f - giou;
        }
    }

    // block reduction
    #pragma unroll
    for (int o = 16; o; o >>= 1) {
        fl  += __shfl_down_sync(0xFFFFFFFFu, fl, o);
        ll  += __shfl_down_sync(0xFFFFFFFFu, ll, o);
        pos += __shfl_down_sync(0xFFFFFFFFu, pos, o);
    }
    int wid = tid >> 5, lid = tid & 31;
    if (lid == 0) { s_red[wid] = fl; s_red[8 + wid] = ll; s_redi[wid] = pos; }
    __syncthreads();
    if (wid == 0) {
        float f  = (lid < 8) ? s_red[lid]     : 0.0f;
        float l2 = (lid < 8) ? s_red[8 + lid] : 0.0f;
        int   pc = (lid < 8) ? s_redi[lid]    : 0;
        #pragma unroll
        for (int o = 4; o; o >>= 1) {
            f  += __shfl_down_sync(0xFFFFFFFFu, f, o);
            l2 += __shfl_down_sync(0xFFFFFFFFu, l2, o);
            pc += __shfl_down_sync(0xFFFFFFFFu, pc, o);
        }
        if (lid == 0) {
            atomicAdd(&g_conf_sum, (double)f);
            atomicAdd(&g_loc_sum, (double)l2);
            atomicAdd(&g_npos, pc);
        }
    }
}

// ---------------------------------------------------------------------------
__global__ void k_final(float* __restrict__ out) {
    int np = g_npos;
    double denom = (double)(np > 0 ? np : 1);
    float res = (float)(g_loc_sum / denom) + (float)(g_conf_sum / denom);
    out[0] = (np == 0) ? 0.0f : res;
}

// ---------------------------------------------------------------------------
extern "C" void kernel_launch(void* const* d_in, const int* in_sizes, int n_in,
                              void* d_out, int out_size) {
    const float4* loc  = (const float4*)d_in[0];  // [B,P,4]  f32
    const float*  conf = (const float*)d_in[1];   // [B,P,21] f32
    const float4* dbox = (const float4*)d_in[2];  // [P,4]    f32
    const float4* gt   = (const float4*)d_in[3];  // [B,50,4] f32
    const int*    glab = (const int*)d_in[4];     // [B,50]   i32
    float* out = (float*)d_out;

    k_init<<<(BB * MM + 255) / 256, 256>>>();
    dim3 grid(GX, BB);
    k_match<<<grid, 256>>>(dbox, gt);
    k_loss<<<grid, 256>>>(loc, conf, dbox, gt, glab);
    k_final<<<1, 1>>>(out);
}

// round 2
// speedup vs baseline: 1.2146x; 1.2146x over previous
#include <cuda_runtime.h>

#define BB 64
#define PP 24564
#define MM 50
#define CC 21
#define TPB 256
#define PPT 2
#define GXM ((PP + TPB * PPT - 1) / (TPB * PPT))   // 48 blocks (x) for k_match
#define GXL ((PP + TPB - 1) / TPB)                 // 96 blocks (x) for k_loss
#define NBLK_LOSS (GXL * BB)                       // 6144

// ---- scratch (static __device__, zero-initialized at module load; the
// ---- finalize path restores everything to zero each run) ----
__device__ unsigned long long g_bp[BB * MM];  // packed (iou_bits<<32)|(~p)
__device__ int      g_bt_idx[BB * PP];
__device__ float    g_bt_iou[BB * PP];
__device__ double   g_loc_sum;
__device__ double   g_conf_sum;
__device__ int      g_npos;
__device__ unsigned g_done;

// ---------------------------------------------------------------------------
// Matching: 2 priors per thread. Per-prior best GT (first-max argmax over M)
// and per-GT best prior (max IoU, lowest-p tiebreak) via packed u64 atomicMax.
__global__ void __launch_bounds__(TPB) k_match(const float4* __restrict__ dbox,
                                               const float4* __restrict__ gt)
{
    __shared__ float4 s_g[MM];
    __shared__ float  s_a[MM];
    __shared__ unsigned long long s_best[MM];

    int tid = threadIdx.x;
    int b = blockIdx.y;
    if (tid < MM) {
        float4 g = gt[b * MM + tid];
        s_g[tid] = g;
        s_a[tid] = (g.z - g.x) * (g.w - g.y);
        s_best[tid] = 0ull;
    }
    __syncthreads();

    int p1 = blockIdx.x * (TPB * PPT) + tid;
    int p2 = p1 + TPB;
    bool v2 = (p2 < PP);
    int p2c = v2 ? p2 : (PP - 1);       // clamp: duplicate of PP-1 can only tie,
                                        // and ties resolve to the real thread
    float4 d1 = dbox[p1];
    float4 d2 = dbox[p2c];
    float a1 = (d1.z - d1.x) * (d1.w - d1.y);
    float a2 = (d2.z - d2.x) * (d2.w - d2.y);
    float best1 = -1.0f, best2 = -1.0f;
    int bm1 = 0, bm2 = 0;
    unsigned ip1 = 0xFFFFFFFFu - (unsigned)p1;
    unsigned ip2 = 0xFFFFFFFFu - (unsigned)p2c;

    #pragma unroll 10
    for (int m = 0; m < MM; m++) {
        float4 g = s_g[m];
        float am = s_a[m];
        // prior 1
        float ix0 = fmaxf(d1.x, g.x), iy0 = fmaxf(d1.y, g.y);
        float ix1 = fminf(d1.z, g.z), iy1 = fminf(d1.w, g.w);
        float iw  = fmaxf(ix1 - ix0, 0.0f), ih = fmaxf(iy1 - iy0, 0.0f);
        float in1 = iw * ih;
        float iou1 = __fdividef(in1, a1 + am - in1);
        if (iou1 > best1) { best1 = iou1; bm1 = m; }   // strict > = first-max
        // prior 2
        float jx0 = fmaxf(d2.x, g.x), jy0 = fmaxf(d2.y, g.y);
        float jx1 = fminf(d2.z, g.z), jy1 = fminf(d2.w, g.w);
        float jw  = fmaxf(jx1 - jx0, 0.0f), jh = fmaxf(jy1 - jy0, 0.0f);
        float in2 = jw * jh;
        float iou2 = __fdividef(in2, a2 + am - in2);
        if (iou2 > best2) { best2 = iou2; bm2 = m; }
        // per-GT best guard (one LDS serves both priors; stale reads only
        // under-admit the guard, never skip a needed update)
        float cur = __uint_as_float(((const unsigned*)&s_best[m])[1]);
        if (iou1 > cur)
            atomicMax(&s_best[m],
                      ((unsigned long long)__float_as_uint(iou1) << 32) | ip1);
        if (iou2 > cur)
            atomicMax(&s_best[m],
                      ((unsigned long long)__float_as_uint(iou2) << 32) | ip2);
    }

    g_bt_idx[b * PP + p1] = bm1;
    g_bt_iou[b * PP + p1] = best1;
    if (v2) {
        g_bt_idx[b * PP + p2] = bm2;
        g_bt_iou[b * PP + p2] = best2;
    }
    __syncthreads();
    if (tid < MM) atomicMax(&g_bp[b * MM + tid], s_best[tid]);
}

// ---------------------------------------------------------------------------
// Fused: force-match + labels + focal + GIoU + reductions + finalize/reset.
__global__ void __launch_bounds__(TPB) k_loss(const float4* __restrict__ loc,
                                              const float*  __restrict__ conf,
                                              const float4* __restrict__ dbox,
                                              const float4* __restrict__ gt,
                                              const int*    __restrict__ glab,
                                              float* __restrict__ out)
{
    __shared__ float4 s_g[MM];
    __shared__ int    s_lab[MM];
    __shared__ int    s_force[TPB];         // force-match map: m or -1
    __shared__ float4 s_conf4[TPB * CC / 4];
    __shared__ float  s_red[16];
    __shared__ int    s_redi[8];
    __shared__ int    s_last;

    int tid = threadIdx.x;
    int b = blockIdx.y;
    int p0 = blockIdx.x * TPB;
    int rows = min(TPB, PP - p0);

    s_force[tid] = -1;
    if (tid < MM) {
        s_g[tid]   = gt[b * MM + tid];
        s_lab[tid] = glab[b * MM + tid];
    }
    __syncthreads();
    if (tid < MM) {
        unsigned long long pk = g_bp[b * MM + tid];
        int bp = (int)(0xFFFFFFFFu - (unsigned)(pk & 0xFFFFFFFFull));
        if (bp >= p0 && bp < p0 + rows)
            atomicMax(&s_force[bp - p0], tid);   // duplicate -> largest m wins
    }
    // stage conf rows: float4-coalesced ((b*PP+p0)*21 and rows*21 are /4)
    {
        const float4* c4 = (const float4*)(conf + ((size_t)b * PP + (size_t)p0) * CC);
        int n4 = rows * CC / 4;
        for (int i = tid; i < n4; i += TPB) s_conf4[i] = c4[i];
    }
    __syncthreads();

    float fl = 0.0f, ll = 0.0f;
    int pos = 0;
    int p = p0 + tid;
    if (tid < rows) {
        int   idx = g_bt_idx[b * PP + p];
        float iou = g_bt_iou[b * PP + p];
        int fm = s_force[tid];
        if (fm >= 0) { idx = fm; iou = 2.0f; }
        int lab = (iou < 0.5f) ? 0 : s_lab[idx];
        pos = (lab > 0) ? 1 : 0;

        // focal loss: logsumexp over 21 classes; stride-21 LDS conflict-free
        const float* row = (const float*)s_conf4 + tid * CC;
        float mx = row[0];
        #pragma unroll
        for (int c = 1; c < CC; c++) mx = fmaxf(mx, row[c]);
        float sum = 0.0f;
        #pragma unroll
        for (int c = 0; c < CC; c++) sum += __expf(row[c] - mx);
        float ce = mx + __logf(sum) - row[lab];
        float pt = __expf(-ce);
        float om = fmaxf(1.0f - pt, 0.0f);
        fl = 0.5f * om * sqrtf(om) * ce;        // ALPHA*(1-pt)^GAMMA, GAMMA=1.5

        if (pos) {
            float4 d = dbox[p];
            float4 g = s_g[idx];
            float dw = d.z - d.x, dh = d.w - d.y;
            float dcx = d.x + 0.5f * dw, dcy = d.y + 0.5f * dh;
            float gw = g.z - g.x, gh = g.w - g.y;
            float gcx = g.x + 0.5f * gw, gcy = g.y + 0.5f * gh;
            float ex = __fdividef(gcx - dcx, dw + 1e-8f);
            float ey = __fdividef(gcy - dcy, dh + 1e-8f);
            float ew = __logf(__fdividef(gw, dw + 1e-8f) + 1e-8f);
            float eh = __logf(__fdividef(gh, dh + 1e-8f) + 1e-8f);
            float tcx = ex * dw + dcx, tcy = ey * dh + dcy;
            float tw = __expf(ew) * dw, th = __expf(eh) * dh;
            float tx0 = tcx - 0.5f * tw, ty0 = tcy - 0.5f * th;
            float tx1 = tcx + 0.5f * tw, ty1 = tcy + 0.5f * th;
            float4 l = loc[(size_t)b * PP + p];
            float pcx = l.x * dw + dcx, pcy = l.y * dh + dcy;
            float pw = __expf(l.z) * dw, ph = __expf(l.w) * dh;
            float px0 = pcx - 0.5f * pw, py0 = pcy - 0.5f * ph;
            float px1 = pcx + 0.5f * pw, py1 = pcy + 0.5f * ph;
            float ix0 = fmaxf(px0, tx0), iy0 = fmaxf(py0, ty0);
            float ix1 = fminf(px1, tx1), iy1 = fminf(py1, ty1);
            float iw = fmaxf(ix1 - ix0, 0.0f), ih = fmaxf(iy1 - iy0, 0.0f);
            float inter = iw * ih;
            float pa = (px1 - px0) * (py1 - py0);
            float ta = (tx1 - tx0) * (ty1 - ty0);
            float uni = pa + ta - inter;
            float i2 = __fdividef(inter, uni + 1e-7f);
            float e0x = fminf(px0, tx0), e0y = fminf(py0, ty0);
            float e1x = fmaxf(px1, tx1), e1y = fmaxf(py1, ty1);
            float ewd = fmaxf(e1x - e0x, 0.0f), ehd = fmaxf(e1y - e0y, 0.0f);
            float encl = ewd * ehd;
            float giou = i2 - __fdividef(encl - uni, encl + 1e-7f);
            ll = 1.0f - giou;
        }
    }

    // block reduction
    #pragma unroll
    for (int o = 16; o; o >>= 1) {
        fl  += __shfl_down_sync(0xFFFFFFFFu, fl, o);
        ll  += __shfl_down_sync(0xFFFFFFFFu, ll, o);
        pos += __shfl_down_sync(0xFFFFFFFFu, pos, o);
    }
    int wid = tid >> 5, lid = tid & 31;
    if (lid == 0) { s_red[wid] = fl; s_red[8 + wid] = ll; s_redi[wid] = pos; }
    __syncthreads();
    if (wid == 0) {
        float f  = (lid < 8) ? s_red[lid]     : 0.0f;
        float l2 = (lid < 8) ? s_red[8 + lid] : 0.0f;
        int   pc = (lid < 8) ? s_redi[lid]    : 0;
        #pragma unroll
        for (int o = 4; o; o >>= 1) {
            f  += __shfl_down_sync(0xFFFFFFFFu, f, o);
            l2 += __shfl_down_sync(0xFFFFFFFFu, l2, o);
            pc += __shfl_down_sync(0xFFFFFFFFu, pc, o);
        }
        if (lid == 0) {
            atomicAdd(&g_conf_sum, (double)f);
            atomicAdd(&g_loc_sum, (double)l2);
            atomicAdd(&g_npos, pc);
        }
    }

    // ---- last-block finalize + scratch reset (replaces k_final/k_init) ----
    if (tid == 0) {
        __threadfence();
        unsigned t = atomicAdd(&g_done, 1u);
        s_last = (t == (unsigned)(NBLK_LOSS - 1)) ? 1 : 0;
    }
    __syncthreads();
    if (s_last) {
        __threadfence();
        if (tid == 0) {
            double ls = atomicAdd(&g_loc_sum, 0.0);
            double cs = atomicAdd(&g_conf_sum, 0.0);
            int np = atomicAdd(&g_npos, 0);
            double denom = (double)(np > 0 ? np : 1);
            float res = (float)(ls / denom) + (float)(cs / denom);
            out[0] = (np == 0) ? 0.0f : res;
            g_loc_sum = 0.0; g_conf_sum = 0.0; g_npos = 0; g_done = 0u;
        }
        for (int i = tid; i < BB * MM; i += TPB) g_bp[i] = 0ull;
    }
}

// ---------------------------------------------------------------------------
extern "C" void kernel_launch(void* const* d_in, const int* in_sizes, int n_in,
                              void* d_out, int out_size) {
    const float4* loc  = (const float4*)d_in[0];  // [B,P,4]  f32
    const float*  conf = (const float*)d_in[1];   // [B,P,21] f32
    const float4* dbox = (const float4*)d_in[2];  // [P,4]    f32
    const float4* gt   = (const float4*)d_in[3];  // [B,50,4] f32
    const int*    glab = (const int*)d_in[4];     // [B,50]   i32
    float* out = (float*)d_out;

    dim3 gm(GXM, BB);
    k_match<<<gm, TPB>>>(dbox, gt);
    dim3 gl(GXL, BB);
    k_loss<<<gl, TPB>>>(loc, conf, dbox, gt, glab, out);
}

// round 3
// speedup vs baseline: 1.2335x; 1.0156x over previous
#include <cuda_runtime.h>

#define BB 64
#define PP 24564
#define MM 50
#define CC 21
#define TPB 256
#define RPB 512                           // priors per block (fused kernel)
#define GXF ((PP + RPB - 1) / RPB)        // 48
#define NBLK_FIX BB

// ---- scratch (zero-init at load; k_fix restores zeros every run) ----
__device__ unsigned long long g_bp[BB * MM];  // packed (iou_bits<<32)|(~p)
__device__ int      g_bt_idx[BB * PP];
__device__ float    g_bt_iou[BB * PP];
__device__ double   g_loc_sum;
__device__ double   g_conf_sum;
__device__ int      g_npos;
__device__ unsigned g_done;

// ---------------------------------------------------------------------------
// Shared helpers — used by BOTH kernels so provisional terms cancel exactly.
__device__ __forceinline__ float focal_term(const float* __restrict__ row, int lab) {
    float mx = row[0];
    #pragma unroll
    for (int c = 1; c < CC; c++) mx = fmaxf(mx, row[c]);
    float sum = 0.0f;
    #pragma unroll
    for (int c = 0; c < CC; c++) sum += __expf(row[c] - mx);
    float ce = mx + __logf(sum) - row[lab];
    float pt = __expf(-ce);
    float om = fmaxf(1.0f - pt, 0.0f);
    return 0.5f * om * sqrtf(om) * ce;        // ALPHA*(1-pt)^GAMMA*ce, GAMMA=1.5
}

__device__ __forceinline__ float loc_term(float4 d, float4 g, float4 l) {
    float dw = d.z - d.x, dh = d.w - d.y;
    float dcx = d.x + 0.5f * dw, dcy = d.y + 0.5f * dh;
    float gw = g.z - g.x, gh = g.w - g.y;
    float gcx = g.x + 0.5f * gw, gcy = g.y + 0.5f * gh;
    // encode (EPS8)
    float ex = __fdividef(gcx - dcx, dw + 1e-8f);
    float ey = __fdividef(gcy - dcy, dh + 1e-8f);
    float ew = __logf(__fdividef(gw, dw + 1e-8f) + 1e-8f);
    float eh = __logf(__fdividef(gh, dh + 1e-8f) + 1e-8f);
    // decode target
    float tcx = ex * dw + dcx, tcy = ey * dh + dcy;
    float tw = __expf(ew) * dw, th = __expf(eh) * dh;
    float tx0 = tcx - 0.5f * tw, ty0 = tcy - 0.5f * th;
    float tx1 = tcx + 0.5f * tw, ty1 = tcy + 0.5f * th;
    // decode prediction
    float pcx = l.x * dw + dcx, pcy = l.y * dh + dcy;
    float pw = __expf(l.z) * dw, ph = __expf(l.w) * dh;
    float px0 = pcx - 0.5f * pw, py0 = pcy - 0.5f * ph;
    float px1 = pcx + 0.5f * pw, py1 = pcy + 0.5f * ph;
    // GIoU (EPS7)
    float ix0 = fmaxf(px0, tx0), iy0 = fmaxf(py0, ty0);
    float ix1 = fminf(px1, tx1), iy1 = fminf(py1, ty1);
    float iw = fmaxf(ix1 - ix0, 0.0f), ih = fmaxf(iy1 - iy0, 0.0f);
    float inter = iw * ih;
    float pa = (px1 - px0) * (py1 - py0);
    float ta = (tx1 - tx0) * (ty1 - ty0);
    float uni = pa + ta - inter;
    float i2 = __fdividef(inter, uni + 1e-7f);
    float e0x = fminf(px0, tx0), e0y = fminf(py0, ty0);
    float e1x = fmaxf(px1, tx1), e1y = fmaxf(py1, ty1);
    float ewd = fmaxf(e1x - e0x, 0.0f), ehd = fmaxf(e1y - e0y, 0.0f);
    float encl = ewd * ehd;
    float giou = i2 - __fdividef(encl - uni, encl + 1e-7f);
    return 1.0f - giou;
}

// ---------------------------------------------------------------------------
// Fused: matching + PROVISIONAL (pre-force-match) focal + GIoU losses.
// conf tile staged via cp.async so the DRAM stream hides under match compute.
__global__ void __launch_bounds__(TPB) k_main(const float4* __restrict__ loc,
                                              const float*  __restrict__ conf,
                                              const float4* __restrict__ dbox,
                                              const float4* __restrict__ gt,
                                              const int*    __restrict__ glab)
{
    __shared__ float4 s_g[MM];
    __shared__ float  s_a[MM];
    __shared__ unsigned long long s_best[MM];
    __shared__ int    s_lab[MM];
    __shared__ float  s_conf[RPB * CC];       // 43008 B
    __shared__ float  s_red[16];
    __shared__ int    s_redi[8];

    int tid = threadIdx.x;
    int b = blockIdx.y;
    int p0 = blockIdx.x * RPB;
    int rows = min(RPB, PP - p0);             // 512 or 500; both %4==0

    // ---- stage conf (issued first; lands while we do the match loop) ----
    {
        const char* gsrc = (const char*)(conf + ((size_t)b * PP + (size_t)p0) * CC);
        unsigned sdst = (unsigned)__cvta_generic_to_shared(s_conf);
        int n16 = rows * CC / 4;              // 16B chunks
        for (int i = tid; i < n16; i += TPB) {
            asm volatile("cp.async.ca.shared.global [%0], [%1], 16;\n"
                         :: "r"(sdst + i * 16), "l"(gsrc + (size_t)i * 16));
        }
        asm volatile("cp.async.commit_group;\n");
    }

    if (tid < MM) {
        float4 g = gt[b * MM + tid];
        s_g[tid] = g;
        s_a[tid] = (g.z - g.x) * (g.w - g.y);
        s_best[tid] = 0ull;
        s_lab[tid] = glab[b * MM + tid];
    }
    __syncthreads();

    // ---- match loop: 2 priors per thread ----
    int p1 = p0 + tid;
    int p2 = p1 + TPB;
    bool v2 = (p2 < PP);
    int p2c = v2 ? p2 : (PP - 1);             // duplicate can only tie; tie loses
    float4 d1 = dbox[p1];
    float4 d2 = dbox[p2c];
    float a1 = (d1.z - d1.x) * (d1.w - d1.y);
    float a2 = (d2.z - d2.x) * (d2.w - d2.y);
    float best1 = -1.0f, best2 = -1.0f;
    int bm1 = 0, bm2 = 0;
    unsigned ip1 = 0xFFFFFFFFu - (unsigned)p1;
    unsigned ip2 = 0xFFFFFFFFu - (unsigned)p2c;

    #pragma unroll 10
    for (int m = 0; m < MM; m++) {
        float4 g = s_g[m];
        float am = s_a[m];
        float ix0 = fmaxf(d1.x, g.x), iy0 = fmaxf(d1.y, g.y);
        float ix1 = fminf(d1.z, g.z), iy1 = fminf(d1.w, g.w);
        float iw  = fmaxf(ix1 - ix0, 0.0f), ih = fmaxf(iy1 - iy0, 0.0f);
        float in1 = iw * ih;
        float iou1 = __fdividef(in1, a1 + am - in1);
        if (iou1 > best1) { best1 = iou1; bm1 = m; }   // strict > = first-max
        float jx0 = fmaxf(d2.x, g.x), jy0 = fmaxf(d2.y, g.y);
        float jx1 = fminf(d2.z, g.z), jy1 = fminf(d2.w, g.w);
        float jw  = fmaxf(jx1 - jx0, 0.0f), jh = fmaxf(jy1 - jy0, 0.0f);
        float in2 = jw * jh;
        float iou2 = __fdividef(in2, a2 + am - in2);
        if (iou2 > best2) { best2 = iou2; bm2 = m; }
        // guarded per-GT best (stale guard reads only under-admit)
        float cur = __uint_as_float(((const unsigned*)&s_best[m])[1]);
        if (iou1 > cur)
            atomicMax(&s_best[m],
                      ((unsigned long long)__float_as_uint(iou1) << 32) | ip1);
        if (iou2 > cur)
            atomicMax(&s_best[m],
                      ((unsigned long long)__float_as_uint(iou2) << 32) | ip2);
    }

    g_bt_idx[b * PP + p1] = bm1;
    g_bt_iou[b * PP + p1] = best1;
    if (v2) {
        g_bt_idx[b * PP + p2] = bm2;
        g_bt_iou[b * PP + p2] = best2;
    }
    __syncthreads();
    if (tid < MM) atomicMax(&g_bp[b * MM + tid], s_best[tid]);

    asm volatile("cp.async.wait_group 0;\n" ::: "memory");
    __syncthreads();

    // ---- provisional focal + GIoU for this thread's 2 priors ----
    float fl = 0.0f, ll = 0.0f;
    int pos = 0;
    {
        int lab = (best1 < 0.5f) ? 0 : s_lab[bm1];
        fl += focal_term(s_conf + tid * CC, lab);       // stride 21: conflict-free
        if (lab > 0) {
            pos++;
            ll += loc_term(d1, s_g[bm1], loc[(size_t)b * PP + p1]);
        }
    }
    if (v2) {
        int lab = (best2 < 0.5f) ? 0 : s_lab[bm2];
        fl += focal_term(s_conf + (tid + TPB) * CC, lab);
        if (lab > 0) {
            pos++;
            ll += loc_term(d2, s_g[bm2], loc[(size_t)b * PP + p2]);
        }
    }

    // ---- block reduction ----
    #pragma unroll
    for (int o = 16; o; o >>= 1) {
        fl  += __shfl_down_sync(0xFFFFFFFFu, fl, o);
        ll  += __shfl_down_sync(0xFFFFFFFFu, ll, o);
        pos += __shfl_down_sync(0xFFFFFFFFu, pos, o);
    }
    int wid = tid >> 5, lid = tid & 31;
    if (lid == 0) { s_red[wid] = fl; s_red[8 + wid] = ll; s_redi[wid] = pos; }
    __syncthreads();
    if (wid == 0) {
        float f  = (lid < 8) ? s_red[lid]     : 0.0f;
        float l2 = (lid < 8) ? s_red[8 + lid] : 0.0f;
        int   pc = (lid < 8) ? s_redi[lid]    : 0;
        #pragma unroll
        for (int o = 4; o; o >>= 1) {
            f  += __shfl_down_sync(0xFFFFFFFFu, f, o);
            l2 += __shfl_down_sync(0xFFFFFFFFu, l2, o);
            pc += __shfl_down_sync(0xFFFFFFFFu, pc, o);
        }
        if (lid == 0) {
            atomicAdd(&g_conf_sum, (double)f);
            atomicAdd(&g_loc_sum, (double)l2);
            atomicAdd(&g_npos, pc);
        }
    }
}

// ---------------------------------------------------------------------------
// Fixup (≤50 forced priors per batch) + finalize + scratch reset.
__global__ void __launch_bounds__(64) k_fix(const float4* __restrict__ loc,
                                            const float*  __restrict__ conf,
                                            const float4* __restrict__ dbox,
                                            const float4* __restrict__ gt,
                                            const int*    __restrict__ glab,
                                            float* __restrict__ out)
{
    __shared__ int    s_bp[MM];
    __shared__ float4 s_g[MM];
    __shared__ int    s_lab[MM];
    __shared__ float  s_f[2], s_l[2];
    __shared__ int    s_p[2];

    int tid = threadIdx.x;
    int b = blockIdx.x;

    if (tid < MM) {
        unsigned long long pk = g_bp[b * MM + tid];
        s_bp[tid]  = (int)(0xFFFFFFFFu - (unsigned)(pk & 0xFFFFFFFFull));
        s_g[tid]   = gt[b * MM + tid];
        s_lab[tid] = glab[b * MM + tid];
        g_bp[b * MM + tid] = 0ull;          // reset for next run
    }
    __syncthreads();

    float dconf = 0.0f, dloc = 0.0f;
    int dpos = 0;
    if (tid < MM) {
        int p = s_bp[tid];
        bool win = (p >= 0 && p < PP);
        #pragma unroll
        for (int m2 = tid + 1; m2 < MM; m2++)   // duplicate p: largest m wins
            if (s_bp[m2] == p) win = false;
        if (win) {
            int   idx0 = g_bt_idx[b * PP + p];
            float iou0 = g_bt_iou[b * PP + p];
            int lab0 = (iou0 < 0.5f) ? 0 : s_lab[idx0];
            const float* row = conf + ((size_t)b * PP + p) * CC;
            float fl0 = focal_term(row, lab0);          // provisional (cancels)
            float fl1 = focal_term(row, s_lab[tid]);    // forced label
            dconf = fl1 - fl0;
            float4 d = dbox[p];
            float4 l = loc[(size_t)b * PP + p];
            float ll1 = loc_term(d, s_g[tid], l);
            float ll0 = (lab0 > 0) ? loc_term(d, s_g[idx0], l) : 0.0f;
            dloc = ll1 - ll0;
            dpos = 1 - ((lab0 > 0) ? 1 : 0);
        }
    }

    // reduce over 2 warps
    #pragma unroll
    for (int o = 16; o; o >>= 1) {
        dconf += __shfl_down_sync(0xFFFFFFFFu, dconf, o);
        dloc  += __shfl_down_sync(0xFFFFFFFFu, dloc, o);
        dpos  += __shfl_down_sync(0xFFFFFFFFu, dpos, o);
    }
    int wid = tid >> 5, lid = tid & 31;
    if (lid == 0) { s_f[wid] = dconf; s_l[wid] = dloc; s_p[wid] = dpos; }
    __syncthreads();
    if (tid == 0) {
        float f = s_f[0] + s_f[1];
        float l = s_l[0] + s_l[1];
        int   pc = s_p[0] + s_p[1];
        if (f != 0.0f) atomicAdd(&g_conf_sum, (double)f);
        if (l != 0.0f) atomicAdd(&g_loc_sum, (double)l);
        if (pc != 0)   atomicAdd(&g_npos, pc);
        __threadfence();
        unsigned t = atomicAdd(&g_done, 1u);
        if (t == (unsigned)(NBLK_FIX - 1)) {
            __threadfence();
            double ls = atomicAdd(&g_loc_sum, 0.0);
            double cs = atomicAdd(&g_conf_sum, 0.0);
            int np = atomicAdd(&g_npos, 0);
            double denom = (double)(np > 0 ? np : 1);
            float res = (float)(ls / denom) + (float)(cs / denom);
            out[0] = (np == 0) ? 0.0f : res;
            g_loc_sum = 0.0; g_conf_sum = 0.0; g_npos = 0; g_done = 0u;
        }
    }
}

// ---------------------------------------------------------------------------
extern "C" void kernel_launch(void* const* d_in, const int* in_sizes, int n_in,
                              void* d_out, int out_size) {
    const float4* loc  = (const float4*)d_in[0];  // [B,P,4]  f32
    const float*  conf = (const float*)d_in[1];   // [B,P,21] f32
    const float4* dbox = (const float4*)d_in[2];  // [P,4]    f32
    const float4* gt   = (const float4*)d_in[3];  // [B,50,4] f32
    const int*    glab = (const int*)d_in[4];     // [B,50]   i32
    float* out = (float*)d_out;

    dim3 gm(GXF, BB);
    k_main<<<gm, TPB>>>(loc, conf, dbox, gt, glab);
    k_fix<<<NBLK_FIX, 64>>>(loc, conf, dbox, gt, glab, out);
}